// round 1
// baseline (speedup 1.0000x reference)
#include <cuda_runtime.h>
#include <math.h>

// Problem shapes (fixed)
#define Bq 2
#define Nq 2048
#define Dq 1024
#define Eq 2048
#define Fq 4096
#define Mq (Bq*Nq)   // 4096 tokens

// ---------------- device scratch (no cudaMalloc allowed) ----------------
__device__ float g_xn  [(size_t)Mq*Dq];   // 16 MB
__device__ float g_Q   [(size_t)Mq*Eq];   // 32 MB
__device__ float g_K   [(size_t)Mq*Eq];   // 32 MB
__device__ float g_V   [(size_t)Mq*Eq];   // 32 MB
__device__ float g_P   [(size_t)Bq*Nq*Nq];// 32 MB (block-causal scores)
__device__ float g_den [Mq];
__device__ float g_attn[(size_t)Mq*Eq];   // 32 MB
__device__ float g_x1  [(size_t)Mq*Dq];   // 16 MB
__device__ float g_xn2 [(size_t)Mq*Dq];   // 16 MB
__device__ float g_h   [(size_t)Mq*Fq];   // 64 MB

// ---------------- LayerNorm: one block per row, D=1024 ----------------
__global__ __launch_bounds__(256)
void ln_kernel(const float* __restrict__ x, const float* __restrict__ g,
               const float* __restrict__ b, float* __restrict__ y)
{
    int row = blockIdx.x;
    int t = threadIdx.x;                       // 256 threads, 4 floats each
    const float4* xr = reinterpret_cast<const float4*>(x + (size_t)row * Dq);
    float4 v = xr[t];
    float s  = v.x + v.y + v.z + v.w;
    float s2 = v.x*v.x + v.y*v.y + v.z*v.z + v.w*v.w;
    __shared__ float rs[8], rs2[8];
    #pragma unroll
    for (int o = 16; o > 0; o >>= 1) {
        s  += __shfl_down_sync(0xffffffffu, s,  o);
        s2 += __shfl_down_sync(0xffffffffu, s2, o);
    }
    if ((t & 31) == 0) { rs[t >> 5] = s; rs2[t >> 5] = s2; }
    __syncthreads();
    float ssum = 0.f, ssum2 = 0.f;
    #pragma unroll
    for (int i = 0; i < 8; i++) { ssum += rs[i]; ssum2 += rs2[i]; }
    float mu   = ssum * (1.0f / Dq);
    float var  = ssum2 * (1.0f / Dq) - mu * mu;
    float rstd = rsqrtf(var + 1e-5f);
    float4 gg = reinterpret_cast<const float4*>(g)[t];
    float4 bb = reinterpret_cast<const float4*>(b)[t];
    float4 o;
    o.x = (v.x - mu) * rstd * gg.x + bb.x;
    o.y = (v.y - mu) * rstd * gg.y + bb.y;
    o.z = (v.z - mu) * rstd * gg.z + bb.z;
    o.w = (v.w - mu) * rstd * gg.w + bb.w;
    reinterpret_cast<float4*>(y + (size_t)row * Dq)[t] = o;
}

// ---------------- generic 128x128x8 SGEMM with fused epilogues ----------------
__device__ __forceinline__ float gelu_exact(float v) {
    return 0.5f * v * (1.0f + erff(v * 0.70710678118654752f));
}

enum { EPI_BIAS = 0, EPI_FEAT = 1, EPI_GELU = 2, EPI_BIAS_RES = 3, EPI_DIV = 4 };

template<int EPI, bool CAUSAL>
__global__ __launch_bounds__(256)
void sgemm_kernel(const float* __restrict__ A, const float* __restrict__ Bm,
                  float* __restrict__ C, int M, int Nn, int K,
                  long long sA, long long sB, long long sC,
                  const float* __restrict__ bias,
                  const float* __restrict__ res, long long sRes,
                  const float* __restrict__ den)
{
    int bz = blockIdx.z;
    const float* Ab = A  + (size_t)bz * sA;
    const float* Bb = Bm + (size_t)bz * sB;
    float*       Cb = C  + (size_t)bz * sC;

    int rowStart = blockIdx.y * 128;
    int colStart = blockIdx.x * 128;
    int keff = CAUSAL ? min(K, ((int)blockIdx.y + 1) * 128) : K;

    __shared__ float As[8][128];
    __shared__ float Bs[8][128];

    int tid  = threadIdx.x;
    int tRow = tid >> 4, tCol = tid & 15;         // 16x16 thread grid, 8x8 each
    int aRow = tid >> 1, aCol = (tid & 1) << 2;   // A tile 128x8 loader
    int bRow = tid >> 5, bCol = (tid & 31) << 2;  // B tile 8x128 loader

    const float* Aptr = Ab + (size_t)(rowStart + aRow) * K + aCol;
    const float* Bptr = Bb + (size_t)bRow * Nn + colStart + bCol;

    float acc[8][8];
    #pragma unroll
    for (int i = 0; i < 8; i++)
        #pragma unroll
        for (int j = 0; j < 8; j++) acc[i][j] = 0.f;

    for (int k0 = 0; k0 < keff; k0 += 8) {
        float4 a4 = *reinterpret_cast<const float4*>(Aptr + k0);
        float4 b4 = *reinterpret_cast<const float4*>(Bptr + (size_t)k0 * Nn);
        __syncthreads();
        As[aCol + 0][aRow] = a4.x;
        As[aCol + 1][aRow] = a4.y;
        As[aCol + 2][aRow] = a4.z;
        As[aCol + 3][aRow] = a4.w;
        *reinterpret_cast<float4*>(&Bs[bRow][bCol]) = b4;
        __syncthreads();
        #pragma unroll
        for (int k = 0; k < 8; k++) {
            float ar[8], br[8];
            *reinterpret_cast<float4*>(ar)     = *reinterpret_cast<const float4*>(&As[k][tRow * 8]);
            *reinterpret_cast<float4*>(ar + 4) = *reinterpret_cast<const float4*>(&As[k][tRow * 8 + 4]);
            *reinterpret_cast<float4*>(br)     = *reinterpret_cast<const float4*>(&Bs[k][tCol * 8]);
            *reinterpret_cast<float4*>(br + 4) = *reinterpret_cast<const float4*>(&Bs[k][tCol * 8 + 4]);
            #pragma unroll
            for (int i = 0; i < 8; i++)
                #pragma unroll
                for (int j = 0; j < 8; j++)
                    acc[i][j] = fmaf(ar[i], br[j], acc[i][j]);
        }
    }

    float bcol[8];
    if (EPI != EPI_DIV) {
        *reinterpret_cast<float4*>(bcol)     = *reinterpret_cast<const float4*>(&bias[colStart + tCol * 8]);
        *reinterpret_cast<float4*>(bcol + 4) = *reinterpret_cast<const float4*>(&bias[colStart + tCol * 8 + 4]);
    }

    #pragma unroll
    for (int i = 0; i < 8; i++) {
        int row = rowStart + tRow * 8 + i;
        float dinv = 1.f;
        if (EPI == EPI_DIV) dinv = 1.0f / den[(size_t)bz * M + row];
        float rv[8];
        if (EPI == EPI_BIAS_RES) {
            const float* rp = res + (size_t)bz * sRes + (size_t)row * Nn + colStart + tCol * 8;
            *reinterpret_cast<float4*>(rv)     = *reinterpret_cast<const float4*>(rp);
            *reinterpret_cast<float4*>(rv + 4) = *reinterpret_cast<const float4*>(rp + 4);
        }
        float outv[8];
        #pragma unroll
        for (int j = 0; j < 8; j++) {
            float v = acc[i][j];
            if (EPI == EPI_BIAS)      v += bcol[j];
            if (EPI == EPI_FEAT)     { v += bcol[j]; v = (v > 0.f) ? (v + 1.f) : expf(v); }
            if (EPI == EPI_GELU)     { v += bcol[j]; v = gelu_exact(v); }
            if (EPI == EPI_BIAS_RES)  v += bcol[j] + rv[j];
            if (EPI == EPI_DIV)       v *= dinv;
            outv[j] = v;
        }
        float* cp = Cb + (size_t)row * Nn + colStart + tCol * 8;
        *reinterpret_cast<float4*>(cp)     = *reinterpret_cast<const float4*>(outv);
        *reinterpret_cast<float4*>(cp + 4) = *reinterpret_cast<const float4*>(outv + 4);
    }
}

// ---------------- scores: P = tril(Q K^T) per batch; den += rowsum ----------------
__global__ __launch_bounds__(256)
void score_kernel(const float* __restrict__ Qm, const float* __restrict__ Km,
                  float* __restrict__ P, float* __restrict__ den)
{
    int bz = blockIdx.z;
    int rt = blockIdx.y, ct = blockIdx.x;
    if (ct > rt) return;                    // strictly block-causal: skip upper tiles

    const float* Qb = Qm + (size_t)bz * Nq * Eq;
    const float* Kb = Km + (size_t)bz * Nq * Eq;
    float*       Pb = P  + (size_t)bz * Nq * Nq;

    int rowStart = rt * 128, colStart = ct * 128;

    __shared__ float Qs[8][128];
    __shared__ float Ks[8][128];

    int tid  = threadIdx.x;
    int tRow = tid >> 4, tCol = tid & 15;
    int lRow = tid >> 1, lCol = (tid & 1) << 2;

    const float* Qptr = Qb + (size_t)(rowStart + lRow) * Eq + lCol;
    const float* Kptr = Kb + (size_t)(colStart + lRow) * Eq + lCol;

    float acc[8][8];
    #pragma unroll
    for (int i = 0; i < 8; i++)
        #pragma unroll
        for (int j = 0; j < 8; j++) acc[i][j] = 0.f;

    for (int k0 = 0; k0 < Eq; k0 += 8) {
        float4 q4 = *reinterpret_cast<const float4*>(Qptr + k0);
        float4 k4 = *reinterpret_cast<const float4*>(Kptr + k0);
        __syncthreads();
        Qs[lCol + 0][lRow] = q4.x; Qs[lCol + 1][lRow] = q4.y;
        Qs[lCol + 2][lRow] = q4.z; Qs[lCol + 3][lRow] = q4.w;
        Ks[lCol + 0][lRow] = k4.x; Ks[lCol + 1][lRow] = k4.y;
        Ks[lCol + 2][lRow] = k4.z; Ks[lCol + 3][lRow] = k4.w;
        __syncthreads();
        #pragma unroll
        for (int k = 0; k < 8; k++) {
            float qr[8], kr[8];
            *reinterpret_cast<float4*>(qr)     = *reinterpret_cast<const float4*>(&Qs[k][tRow * 8]);
            *reinterpret_cast<float4*>(qr + 4) = *reinterpret_cast<const float4*>(&Qs[k][tRow * 8 + 4]);
            *reinterpret_cast<float4*>(kr)     = *reinterpret_cast<const float4*>(&Ks[k][tCol * 8]);
            *reinterpret_cast<float4*>(kr + 4) = *reinterpret_cast<const float4*>(&Ks[k][tCol * 8 + 4]);
            #pragma unroll
            for (int i = 0; i < 8; i++)
                #pragma unroll
                for (int j = 0; j < 8; j++)
                    acc[i][j] = fmaf(qr[i], kr[j], acc[i][j]);
        }
    }

    #pragma unroll
    for (int i = 0; i < 8; i++) {
        int row = rowStart + tRow * 8 + i;
        float rsum = 0.f;
        float outv[8];
        #pragma unroll
        for (int j = 0; j < 8; j++) {
            int col = colStart + tCol * 8 + j;
            float v = acc[i][j];
            if (col > row) v = 0.f;        // intra-tile causal mask
            rsum += v;
            outv[j] = v;
        }
        float* pp = Pb + (size_t)row * Nq + colStart + tCol * 8;
        *reinterpret_cast<float4*>(pp)     = *reinterpret_cast<const float4*>(outv);
        *reinterpret_cast<float4*>(pp + 4) = *reinterpret_cast<const float4*>(outv + 4);
        atomicAdd(&den[(size_t)bz * Nq + row], rsum);
    }
}

__global__ void den_init(float* den) {
    den[blockIdx.x * 256 + threadIdx.x] = 1e-6f;
}

// ---------------- launch ----------------
extern "C" void kernel_launch(void* const* d_in, const int* in_sizes, int n_in,
                              void* d_out, int out_size)
{
    const float* x     = (const float*)d_in[0];
    const float* q_w   = (const float*)d_in[1];
    const float* q_b   = (const float*)d_in[2];
    const float* k_w   = (const float*)d_in[3];
    const float* k_b   = (const float*)d_in[4];
    const float* v_w   = (const float*)d_in[5];
    const float* v_b   = (const float*)d_in[6];
    const float* o_w   = (const float*)d_in[7];
    const float* o_b   = (const float*)d_in[8];
    const float* ln1_g = (const float*)d_in[9];
    const float* ln1_b = (const float*)d_in[10];
    const float* ln2_g = (const float*)d_in[11];
    const float* ln2_b = (const float*)d_in[12];
    const float* w1    = (const float*)d_in[13];
    const float* b1    = (const float*)d_in[14];
    const float* w2    = (const float*)d_in[15];
    const float* b2    = (const float*)d_in[16];
    float* out = (float*)d_out;

    float *xn, *Qp, *Kp, *Vp, *Pp, *den, *attn, *x1, *xn2, *h;
    cudaGetSymbolAddress((void**)&xn,   g_xn);
    cudaGetSymbolAddress((void**)&Qp,   g_Q);
    cudaGetSymbolAddress((void**)&Kp,   g_K);
    cudaGetSymbolAddress((void**)&Vp,   g_V);
    cudaGetSymbolAddress((void**)&Pp,   g_P);
    cudaGetSymbolAddress((void**)&den,  g_den);
    cudaGetSymbolAddress((void**)&attn, g_attn);
    cudaGetSymbolAddress((void**)&x1,   g_x1);
    cudaGetSymbolAddress((void**)&xn2,  g_xn2);
    cudaGetSymbolAddress((void**)&h,    g_h);

    // LN1
    ln_kernel<<<Mq, 256>>>(x, ln1_g, ln1_b, xn);

    // Q/K/V projections (Q,K fused with elu+1 feature map)
    dim3 gQKV(Eq / 128, Mq / 128, 1);
    sgemm_kernel<EPI_FEAT, false><<<gQKV, 256>>>(xn, q_w, Qp, Mq, Eq, Dq, 0, 0, 0, q_b, nullptr, 0, nullptr);
    sgemm_kernel<EPI_FEAT, false><<<gQKV, 256>>>(xn, k_w, Kp, Mq, Eq, Dq, 0, 0, 0, k_b, nullptr, 0, nullptr);
    sgemm_kernel<EPI_BIAS, false><<<gQKV, 256>>>(xn, v_w, Vp, Mq, Eq, Dq, 0, 0, 0, v_b, nullptr, 0, nullptr);

    // Attention: P = tril(Q K^T), den = rowsum(P) + 1e-6, attn = (P @ V) / den
    den_init<<<Mq / 256, 256>>>(den);
    score_kernel<<<dim3(Nq / 128, Nq / 128, Bq), 256>>>(Qp, Kp, Pp, den);
    sgemm_kernel<EPI_DIV, true><<<dim3(Eq / 128, Nq / 128, Bq), 256>>>(
        Pp, Vp, attn, Nq, Eq, Nq,
        (long long)Nq * Nq, (long long)Nq * Eq, (long long)Nq * Eq,
        nullptr, nullptr, 0, den);

    // Output projection + residual
    sgemm_kernel<EPI_BIAS_RES, false><<<dim3(Dq / 128, Mq / 128, 1), 256>>>(
        attn, o_w, x1, Mq, Dq, Eq, 0, 0, 0, o_b, x, 0, nullptr);

    // LN2 + FFN (+ residual)
    ln_kernel<<<Mq, 256>>>(x1, ln2_g, ln2_b, xn2);
    sgemm_kernel<EPI_GELU, false><<<dim3(Fq / 128, Mq / 128, 1), 256>>>(
        xn2, w1, h, Mq, Fq, Dq, 0, 0, 0, b1, nullptr, 0, nullptr);
    sgemm_kernel<EPI_BIAS_RES, false><<<dim3(Dq / 128, Mq / 128, 1), 256>>>(
        h, w2, out, Mq, Dq, Fq, 0, 0, 0, b2, x1, 0, nullptr);
}

// round 3
// speedup vs baseline: 2.7467x; 2.7467x over previous
#include <cuda_runtime.h>
#include <math.h>
#include <stdint.h>

// Problem shapes (fixed)
#define Bq 2
#define Nq 2048
#define Dq 1024
#define Eq 2048
#define Fq 4096
#define Mq (Bq*Nq)   // 4096 tokens

// ---------------- device scratch (no cudaMalloc allowed) ----------------
__device__ __align__(1024) float g_xn  [(size_t)Mq*Dq];
__device__ __align__(1024) float g_Q   [(size_t)Mq*Eq];
__device__ __align__(1024) float g_K   [(size_t)Mq*Eq];
__device__ __align__(1024) float g_V   [(size_t)Mq*Eq];
__device__ __align__(1024) float g_Vt  [(size_t)Mq*Eq];
__device__ __align__(1024) float g_P   [(size_t)Bq*Nq*Nq];
__device__ __align__(1024) float g_den [Mq];
__device__ __align__(1024) float g_attn[(size_t)Mq*Eq];
__device__ __align__(1024) float g_x1  [(size_t)Mq*Dq];
__device__ __align__(1024) float g_xn2 [(size_t)Mq*Dq];
__device__ __align__(1024) float g_h   [(size_t)Mq*Fq];
__device__ __align__(1024) float g_qT  [(size_t)Dq*Eq];
__device__ __align__(1024) float g_kT  [(size_t)Dq*Eq];
__device__ __align__(1024) float g_vT  [(size_t)Dq*Eq];
__device__ __align__(1024) float g_oT  [(size_t)Dq*Eq];
__device__ __align__(1024) float g_w1T [(size_t)Dq*Fq];
__device__ __align__(1024) float g_w2T [(size_t)Dq*Fq];

// ---------------- helpers ----------------
__device__ __forceinline__ uint32_t smem_u32(const void* p) {
    uint32_t a;
    asm("{ .reg .u64 t; cvta.to.shared.u64 t, %1; cvt.u32.u64 %0, t; }" : "=r"(a) : "l"(p));
    return a;
}
__device__ __forceinline__ float tf32r(float x) {
    asm("cvt.rna.tf32.f32 %0, %1;" : "=f"(x) : "f"(x));
    return x;
}
__device__ __forceinline__ void cp16(uint32_t dst, const void* src) {
    asm volatile("cp.async.cg.shared.global [%0], [%1], 16;" :: "r"(dst), "l"(src) : "memory");
}
#define CP_COMMIT() asm volatile("cp.async.commit_group;" ::: "memory")
#define CP_WAIT2()  asm volatile("cp.async.wait_group 2;" ::: "memory")

__device__ __forceinline__ void ldsm4(uint32_t (&r)[4], uint32_t addr) {
    asm volatile("ldmatrix.sync.aligned.m8n8.x4.shared.b16 {%0,%1,%2,%3}, [%4];"
                 : "=r"(r[0]), "=r"(r[1]), "=r"(r[2]), "=r"(r[3]) : "r"(addr));
}
__device__ __forceinline__ void mma_tf32(float (&c)[4], const uint32_t (&a)[4],
                                         uint32_t b0, uint32_t b1) {
    asm volatile("mma.sync.aligned.m16n8k8.row.col.f32.tf32.tf32.f32 "
                 "{%0,%1,%2,%3}, {%4,%5,%6,%7}, {%8,%9}, {%0,%1,%2,%3};"
                 : "+f"(c[0]), "+f"(c[1]), "+f"(c[2]), "+f"(c[3])
                 : "r"(a[0]), "r"(a[1]), "r"(a[2]), "r"(a[3]), "r"(b0), "r"(b1));
}

// ---------------- elementwise kernels ----------------
__global__ __launch_bounds__(256)
void ln_kernel(const float* __restrict__ x, const float* __restrict__ g,
               const float* __restrict__ b, float* __restrict__ y)
{
    int row = blockIdx.x;
    int t = threadIdx.x;
    const float4* xr = reinterpret_cast<const float4*>(x + (size_t)row * Dq);
    float4 v = xr[t];
    float s  = v.x + v.y + v.z + v.w;
    float s2 = v.x*v.x + v.y*v.y + v.z*v.z + v.w*v.w;
    __shared__ float rs[8], rs2[8];
    #pragma unroll
    for (int o = 16; o > 0; o >>= 1) {
        s  += __shfl_down_sync(0xffffffffu, s,  o);
        s2 += __shfl_down_sync(0xffffffffu, s2, o);
    }
    if ((t & 31) == 0) { rs[t >> 5] = s; rs2[t >> 5] = s2; }
    __syncthreads();
    float ssum = 0.f, ssum2 = 0.f;
    #pragma unroll
    for (int i = 0; i < 8; i++) { ssum += rs[i]; ssum2 += rs2[i]; }
    float mu   = ssum * (1.0f / Dq);
    float var  = ssum2 * (1.0f / Dq) - mu * mu;
    float rstd = rsqrtf(var + 1e-5f);
    float4 gg = reinterpret_cast<const float4*>(g)[t];
    float4 bb = reinterpret_cast<const float4*>(b)[t];
    float4 o;
    o.x = tf32r((v.x - mu) * rstd * gg.x + bb.x);
    o.y = tf32r((v.y - mu) * rstd * gg.y + bb.y);
    o.z = tf32r((v.z - mu) * rstd * gg.z + bb.z);
    o.w = tf32r((v.w - mu) * rstd * gg.w + bb.w);
    reinterpret_cast<float4*>(y + (size_t)row * Dq)[t] = o;
}

__global__ void den_init(float* den) { den[blockIdx.x * 256 + threadIdx.x] = 1e-6f; }

// in [R,C] -> out [C,R], batched in z; output rounded to tf32
__global__ __launch_bounds__(256)
void tr_kernel(const float* __restrict__ in, float* __restrict__ out,
               int R, int C, long long sIn, long long sOut)
{
    __shared__ float t[32][33];
    const float* ib = in  + (size_t)blockIdx.z * sIn;
    float*       ob = out + (size_t)blockIdx.z * sOut;
    int c = blockIdx.x * 32 + threadIdx.x;
    int r = blockIdx.y * 32 + threadIdx.y;
    #pragma unroll
    for (int dy = 0; dy < 32; dy += 8)
        t[threadIdx.y + dy][threadIdx.x] = ib[(size_t)(r + dy) * C + c];
    __syncthreads();
    int c2 = blockIdx.y * 32 + threadIdx.x;
    int r2 = blockIdx.x * 32 + threadIdx.y;
    #pragma unroll
    for (int dy = 0; dy < 32; dy += 8)
        ob[(size_t)(r2 + dy) * R + c2] = tf32r(t[threadIdx.x][threadIdx.y + dy]);
}

// ---------------- tf32 mma.sync GEMM: 128x128 CTA, 8 warps (2Mx4N), warp 64x32 ----------------
__device__ __forceinline__ float gelu_exact(float v) {
    return 0.5f * v * (1.0f + erff(v * 0.70710678118654752f));
}
enum { EPI_BIAS = 0, EPI_FEAT = 1, EPI_GELU = 2, EPI_BIAS_RES = 3, EPI_DIV = 4, EPI_SCORE = 5 };
// CM: 0 none, 1 score-causal (skip upper tiles, mask, rowsum->den), 2 PV (K limited to r0+128)

#define MM_SMEM (3 * 32768 + 1024)

template<int EPI, int CM>
__global__ __launch_bounds__(256, 1)
void mm_kernel(const float* __restrict__ A, const float* __restrict__ Bm, float* __restrict__ C,
               int ldA, int ldB, int ldC, int Kdim,
               long long sA, long long sB, long long sC,
               const float* __restrict__ bias,
               const float* __restrict__ res, long long sRes,
               float* __restrict__ den, int denB)
{
    int bz = blockIdx.z;
    int r0 = blockIdx.y * 128, c0 = blockIdx.x * 128;
    if (CM == 1 && c0 > r0) return;
    const int keff = (CM == 2) ? (r0 + 128) : Kdim;
    const int nc = keff >> 5;                 // 32-wide K chunks (nc >= 4 always)

    const float* Ab = A  + (size_t)bz * sA;
    const float* Bb = Bm + (size_t)bz * sB;
    float*       Cb = C  + (size_t)bz * sC;

    extern __shared__ char dsm[];
    uint32_t s0 = (smem_u32(dsm) + 1023u) & ~1023u;   // stage s: A at s*32768, B at +16384

    int tid = threadIdx.x;

    // ---- loader: each thread does 4 A + 4 B cp.async of 16B per chunk ----
    int lm = tid >> 1;                 // row 0..127
    int cbase = (tid & 1) * 4;         // 16B-chunk base within 8 chunks
    const float* gA = Ab + (size_t)(r0 + lm) * ldA + cbase * 4;
    const float* gB = Bb + (size_t)(c0 + lm) * ldB + cbase * 4;
    uint32_t sw[4];
    #pragma unroll
    for (int i = 0; i < 4; i++)
        sw[i] = (uint32_t)lm * 128u + (uint32_t)(((cbase + i) ^ (lm & 7)) << 4);

    // prologue: chunks 0..2
    #pragma unroll
    for (int j = 0; j < 3; j++) {
        uint32_t aB = s0 + j * 32768, bB = aB + 16384;
        #pragma unroll
        for (int i = 0; i < 4; i++) {
            cp16(aB + sw[i], gA + j * 32 + i * 4);
            cp16(bB + sw[i], gB + j * 32 + i * 4);
        }
        CP_COMMIT();
    }

    // ---- fragment address bases ----
    int lane = tid & 31;
    int wm = (tid >> 5) & 1;           // 2 warps in M (64 rows each)
    int wn = tid >> 6;                 // 4 warps in N (32 cols each)
    int aRow = wm * 64 + (lane & 15);  // + mt*16
    int aHalf = lane >> 4;             // 16B half within k8
    int bg = lane >> 3;
    int bRow = wn * 32 + ((bg >> 1) * 8) + (lane & 7);  // + nt*8, nt in {0,2}
    int bHalf = bg & 1;
    uint32_t aOff = (uint32_t)aRow * 128u;
    uint32_t bOff = (uint32_t)bRow * 128u;
    int aR7 = aRow & 7, bR7 = bRow & 7;

    float c[4][4][4];
    #pragma unroll
    for (int mt = 0; mt < 4; mt++)
        #pragma unroll
        for (int nt = 0; nt < 4; nt++)
            #pragma unroll
            for (int k = 0; k < 4; k++) c[mt][nt][k] = 0.f;

    for (int i = 0; i < nc; i++) {
        int s = i - (i / 3) * 3;
        CP_WAIT2();
        __syncthreads();
        uint32_t aB = s0 + s * 32768, bB = aB + 16384;
        #pragma unroll
        for (int ks = 0; ks < 4; ks++) {
            uint32_t a[4][4];
            #pragma unroll
            for (int mt = 0; mt < 4; mt++) {
                uint32_t ad = aB + aOff + (uint32_t)(mt * 16 * 128)
                            + (uint32_t)(((ks * 2 + aHalf) ^ aR7) << 4);
                ldsm4(a[mt], ad);
            }
            uint32_t b[8];
            #pragma unroll
            for (int np = 0; np < 2; np++) {
                uint32_t bd = bB + bOff + (uint32_t)(np * 16 * 128)
                            + (uint32_t)(((ks * 2 + bHalf) ^ bR7) << 4);
                uint32_t r[4];
                ldsm4(r, bd);
                b[np*4+0]=r[0]; b[np*4+1]=r[1]; b[np*4+2]=r[2]; b[np*4+3]=r[3];
            }
            #pragma unroll
            for (int mt = 0; mt < 4; mt++)
                #pragma unroll
                for (int nt = 0; nt < 4; nt++)
                    mma_tf32(c[mt][nt], a[mt], b[nt*2], b[nt*2+1]);
        }
        __syncthreads();
        if (i + 3 < nc) {
            int j = i + 3;
            uint32_t aB2 = s0 + s * 32768, bB2 = aB2 + 16384;
            #pragma unroll
            for (int ii = 0; ii < 4; ii++) {
                cp16(aB2 + sw[ii], gA + j * 32 + ii * 4);
                cp16(bB2 + sw[ii], gB + j * 32 + ii * 4);
            }
        }
        CP_COMMIT();
    }

    // ---- epilogue ----
    int g4 = lane >> 2, q4 = lane & 3;
    #pragma unroll
    for (int mt = 0; mt < 4; mt++) {
        int row0 = r0 + wm * 64 + mt * 16 + g4;
        int row1 = row0 + 8;
        float d0 = 1.f, d1 = 1.f;
        if (EPI == EPI_DIV) {
            d0 = 1.0f / den[(size_t)bz * denB + row0];
            d1 = 1.0f / den[(size_t)bz * denB + row1];
        }
        float rs0 = 0.f, rs1 = 0.f;
        #pragma unroll
        for (int nt = 0; nt < 4; nt++) {
            int col = c0 + wn * 32 + nt * 8 + q4 * 2;
            float v0 = c[mt][nt][0], v1 = c[mt][nt][1];
            float v2 = c[mt][nt][2], v3 = c[mt][nt][3];
            if (EPI == EPI_BIAS || EPI == EPI_FEAT || EPI == EPI_GELU || EPI == EPI_BIAS_RES) {
                float2 bv = *reinterpret_cast<const float2*>(bias + col);
                v0 += bv.x; v1 += bv.y; v2 += bv.x; v3 += bv.y;
            }
            if (EPI == EPI_FEAT) {
                v0 = tf32r((v0 > 0.f) ? (v0 + 1.f) : expf(v0));
                v1 = tf32r((v1 > 0.f) ? (v1 + 1.f) : expf(v1));
                v2 = tf32r((v2 > 0.f) ? (v2 + 1.f) : expf(v2));
                v3 = tf32r((v3 > 0.f) ? (v3 + 1.f) : expf(v3));
            }
            if (EPI == EPI_GELU) {
                v0 = tf32r(gelu_exact(v0)); v1 = tf32r(gelu_exact(v1));
                v2 = tf32r(gelu_exact(v2)); v3 = tf32r(gelu_exact(v3));
            }
            if (EPI == EPI_BIAS_RES) {
                const float* rp0 = res + (size_t)bz * sRes + (size_t)row0 * ldC + col;
                const float* rp1 = res + (size_t)bz * sRes + (size_t)row1 * ldC + col;
                float2 r0v = *reinterpret_cast<const float2*>(rp0);
                float2 r1v = *reinterpret_cast<const float2*>(rp1);
                v0 += r0v.x; v1 += r0v.y; v2 += r1v.x; v3 += r1v.y;
            }
            if (EPI == EPI_DIV) {
                v0 = tf32r(v0 * d0); v1 = tf32r(v1 * d0);
                v2 = tf32r(v2 * d1); v3 = tf32r(v3 * d1);
            }
            if (EPI == EPI_SCORE) {
                if (col     > row0) v0 = 0.f;
                if (col + 1 > row0) v1 = 0.f;
                if (col     > row1) v2 = 0.f;
                if (col + 1 > row1) v3 = 0.f;
                rs0 += v0 + v1; rs1 += v2 + v3;
                v0 = tf32r(v0); v1 = tf32r(v1); v2 = tf32r(v2); v3 = tf32r(v3);
            }
            float2 o0 = make_float2(v0, v1), o1 = make_float2(v2, v3);
            *reinterpret_cast<float2*>(Cb + (size_t)row0 * ldC + col) = o0;
            *reinterpret_cast<float2*>(Cb + (size_t)row1 * ldC + col) = o1;
        }
        if (EPI == EPI_SCORE) {
            atomicAdd(&den[(size_t)bz * denB + row0], rs0);
            atomicAdd(&den[(size_t)bz * denB + row1], rs1);
        }
    }
}

// ---------------- launch ----------------
extern "C" void kernel_launch(void* const* d_in, const int* in_sizes, int n_in,
                              void* d_out, int out_size)
{
    const float* x     = (const float*)d_in[0];
    const float* q_w   = (const float*)d_in[1];
    const float* q_b   = (const float*)d_in[2];
    const float* k_w   = (const float*)d_in[3];
    const float* k_b   = (const float*)d_in[4];
    const float* v_w   = (const float*)d_in[5];
    const float* v_b   = (const float*)d_in[6];
    const float* o_w   = (const float*)d_in[7];
    const float* o_b   = (const float*)d_in[8];
    const float* ln1_g = (const float*)d_in[9];
    const float* ln1_b = (const float*)d_in[10];
    const float* ln2_g = (const float*)d_in[11];
    const float* ln2_b = (const float*)d_in[12];
    const float* w1    = (const float*)d_in[13];
    const float* b1    = (const float*)d_in[14];
    const float* w2    = (const float*)d_in[15];
    const float* b2    = (const float*)d_in[16];
    float* out = (float*)d_out;

    float *xn, *Qp, *Kp, *Vp, *Vt, *Pp, *den, *attn, *x1, *xn2, *h;
    float *qT, *kT, *vT, *oT, *w1T, *w2T;
    cudaGetSymbolAddress((void**)&xn,   g_xn);
    cudaGetSymbolAddress((void**)&Qp,   g_Q);
    cudaGetSymbolAddress((void**)&Kp,   g_K);
    cudaGetSymbolAddress((void**)&Vp,   g_V);
    cudaGetSymbolAddress((void**)&Vt,   g_Vt);
    cudaGetSymbolAddress((void**)&Pp,   g_P);
    cudaGetSymbolAddress((void**)&den,  g_den);
    cudaGetSymbolAddress((void**)&attn, g_attn);
    cudaGetSymbolAddress((void**)&x1,   g_x1);
    cudaGetSymbolAddress((void**)&xn2,  g_xn2);
    cudaGetSymbolAddress((void**)&h,    g_h);
    cudaGetSymbolAddress((void**)&qT,   g_qT);
    cudaGetSymbolAddress((void**)&kT,   g_kT);
    cudaGetSymbolAddress((void**)&vT,   g_vT);
    cudaGetSymbolAddress((void**)&oT,   g_oT);
    cudaGetSymbolAddress((void**)&w1T,  g_w1T);
    cudaGetSymbolAddress((void**)&w2T,  g_w2T);

    cudaFuncSetAttribute(mm_kernel<EPI_FEAT, 0>,     cudaFuncAttributeMaxDynamicSharedMemorySize, MM_SMEM);
    cudaFuncSetAttribute(mm_kernel<EPI_BIAS, 0>,     cudaFuncAttributeMaxDynamicSharedMemorySize, MM_SMEM);
    cudaFuncSetAttribute(mm_kernel<EPI_SCORE, 1>,    cudaFuncAttributeMaxDynamicSharedMemorySize, MM_SMEM);
    cudaFuncSetAttribute(mm_kernel<EPI_DIV, 2>,      cudaFuncAttributeMaxDynamicSharedMemorySize, MM_SMEM);
    cudaFuncSetAttribute(mm_kernel<EPI_BIAS_RES, 0>, cudaFuncAttributeMaxDynamicSharedMemorySize, MM_SMEM);
    cudaFuncSetAttribute(mm_kernel<EPI_GELU, 0>,     cudaFuncAttributeMaxDynamicSharedMemorySize, MM_SMEM);

    dim3 tb(32, 8);

    // LN1 (tf32-rounded output)
    ln_kernel<<<Mq, 256>>>(x, ln1_g, ln1_b, xn);

    // weight transposes -> [N, K] K-major (tf32-rounded)
    tr_kernel<<<dim3(Eq/32, Dq/32, 1), tb>>>(q_w, qT, Dq, Eq, 0, 0);
    tr_kernel<<<dim3(Eq/32, Dq/32, 1), tb>>>(k_w, kT, Dq, Eq, 0, 0);
    tr_kernel<<<dim3(Eq/32, Dq/32, 1), tb>>>(v_w, vT, Dq, Eq, 0, 0);
    tr_kernel<<<dim3(Dq/32, Eq/32, 1), tb>>>(o_w, oT, Eq, Dq, 0, 0);
    tr_kernel<<<dim3(Fq/32, Dq/32, 1), tb>>>(w1, w1T, Dq, Fq, 0, 0);
    tr_kernel<<<dim3(Dq/32, Fq/32, 1), tb>>>(w2, w2T, Fq, Dq, 0, 0);

    // Q/K/V projections
    mm_kernel<EPI_FEAT, 0><<<dim3(Eq/128, Mq/128, 1), 256, MM_SMEM>>>(
        xn, qT, Qp, Dq, Dq, Eq, Dq, 0, 0, 0, q_b, nullptr, 0, nullptr, 0);
    mm_kernel<EPI_FEAT, 0><<<dim3(Eq/128, Mq/128, 1), 256, MM_SMEM>>>(
        xn, kT, Kp, Dq, Dq, Eq, Dq, 0, 0, 0, k_b, nullptr, 0, nullptr, 0);
    mm_kernel<EPI_BIAS, 0><<<dim3(Eq/128, Mq/128, 1), 256, MM_SMEM>>>(
        xn, vT, Vp, Dq, Dq, Eq, Dq, 0, 0, 0, v_b, nullptr, 0, nullptr, 0);

    // V^T per batch: [Nq, Eq] -> [Eq, Nq] (tf32-rounded)
    tr_kernel<<<dim3(Eq/32, Nq/32, Bq), tb>>>(Vp, Vt, Nq, Eq,
        (long long)Nq * Eq, (long long)Nq * Eq);

    // scores: P = tril(Q K^T); den = rowsum + 1e-6
    den_init<<<Mq/256, 256>>>(den);
    mm_kernel<EPI_SCORE, 1><<<dim3(Nq/128, Nq/128, Bq), 256, MM_SMEM>>>(
        Qp, Kp, Pp, Eq, Eq, Nq, Eq,
        (long long)Nq * Eq, (long long)Nq * Eq, (long long)Nq * Nq,
        nullptr, nullptr, 0, den, Nq);

    // attn = (P @ V) / den  (B operand = V^T, K limited per tile row)
    mm_kernel<EPI_DIV, 2><<<dim3(Eq/128, Nq/128, Bq), 256, MM_SMEM>>>(
        Pp, Vt, attn, Nq, Nq, Eq, Nq,
        (long long)Nq * Nq, (long long)Nq * Eq, (long long)Nq * Eq,
        nullptr, nullptr, 0, den, Nq);

    // output projection + residual
    mm_kernel<EPI_BIAS_RES, 0><<<dim3(Dq/128, Mq/128, 1), 256, MM_SMEM>>>(
        attn, oT, x1, Eq, Eq, Dq, Eq, 0, 0, 0, o_b, x, 0, nullptr, 0);

    // LN2 + FFN
    ln_kernel<<<Mq, 256>>>(x1, ln2_g, ln2_b, xn2);
    mm_kernel<EPI_GELU, 0><<<dim3(Fq/128, Mq/128, 1), 256, MM_SMEM>>>(
        xn2, w1T, h, Dq, Dq, Fq, Dq, 0, 0, 0, b1, nullptr, 0, nullptr, 0);
    mm_kernel<EPI_BIAS_RES, 0><<<dim3(Dq/128, Mq/128, 1), 256, MM_SMEM>>>(
        h, w2T, out, Fq, Fq, Dq, Fq, 0, 0, 0, b2, x1, 0, nullptr, 0);
}

// round 4
// speedup vs baseline: 4.9656x; 1.8079x over previous
#include <cuda_runtime.h>
#include <cuda_fp16.h>
#include <math.h>
#include <stdint.h>

// Problem shapes (fixed)
#define Bq 2
#define Nq 2048
#define Dq 1024
#define Eq 2048
#define Fq 4096
#define Mq (Bq*Nq)   // 4096 tokens

// ---------------- device scratch (no cudaMalloc allowed) ----------------
__device__ __align__(1024) __half g_xn  [(size_t)Mq*Dq];
__device__ __align__(1024) __half g_Q   [(size_t)Mq*Eq];
__device__ __align__(1024) __half g_K   [(size_t)Mq*Eq];
__device__ __align__(1024) __half g_V   [(size_t)Mq*Eq];
__device__ __align__(1024) __half g_Vt  [(size_t)Mq*Eq];
__device__ __align__(1024) __half g_P   [(size_t)Bq*Nq*Nq];
__device__ __align__(1024) float  g_den [Mq];
__device__ __align__(1024) __half g_attn[(size_t)Mq*Eq];
__device__ __align__(1024) float  g_x1  [(size_t)Mq*Dq];
__device__ __align__(1024) __half g_xn2 [(size_t)Mq*Dq];
__device__ __align__(1024) __half g_h   [(size_t)Mq*Fq];
__device__ __align__(1024) __half g_qT  [(size_t)Dq*Eq];
__device__ __align__(1024) __half g_kT  [(size_t)Dq*Eq];
__device__ __align__(1024) __half g_vT  [(size_t)Dq*Eq];
__device__ __align__(1024) __half g_oT  [(size_t)Dq*Eq];
__device__ __align__(1024) __half g_w1T [(size_t)Dq*Fq];
__device__ __align__(1024) __half g_w2T [(size_t)Dq*Fq];

// ---------------- helpers ----------------
__device__ __forceinline__ uint32_t smem_u32(const void* p) {
    uint32_t a;
    asm("{ .reg .u64 t; cvta.to.shared.u64 t, %1; cvt.u32.u64 %0, t; }" : "=r"(a) : "l"(p));
    return a;
}
__device__ __forceinline__ void cp16(uint32_t dst, const void* src) {
    asm volatile("cp.async.cg.shared.global [%0], [%1], 16;" :: "r"(dst), "l"(src) : "memory");
}
#define CP_COMMIT() asm volatile("cp.async.commit_group;" ::: "memory")
#define CP_WAIT2()  asm volatile("cp.async.wait_group 2;" ::: "memory")

__device__ __forceinline__ void ldsm4(uint32_t (&r)[4], uint32_t addr) {
    asm volatile("ldmatrix.sync.aligned.m8n8.x4.shared.b16 {%0,%1,%2,%3}, [%4];"
                 : "=r"(r[0]), "=r"(r[1]), "=r"(r[2]), "=r"(r[3]) : "r"(addr));
}
__device__ __forceinline__ void mma_f16(float (&c)[4], const uint32_t (&a)[4],
                                        uint32_t b0, uint32_t b1) {
    asm volatile("mma.sync.aligned.m16n8k16.row.col.f32.f16.f16.f32 "
                 "{%0,%1,%2,%3}, {%4,%5,%6,%7}, {%8,%9}, {%0,%1,%2,%3};"
                 : "+f"(c[0]), "+f"(c[1]), "+f"(c[2]), "+f"(c[3])
                 : "r"(a[0]), "r"(a[1]), "r"(a[2]), "r"(a[3]), "r"(b0), "r"(b1));
}
__device__ __forceinline__ void st2(float* p, float a, float b) {
    *reinterpret_cast<float2*>(p) = make_float2(a, b);
}
__device__ __forceinline__ void st2(__half* p, float a, float b) {
    *reinterpret_cast<__half2*>(p) = __floats2half2_rn(a, b);
}
__device__ __forceinline__ float ldf(const float* p)  { return *p; }
__device__ __forceinline__ float ldf(const __half* p) { return __half2float(*p); }

// ---------------- elementwise kernels ----------------
__global__ __launch_bounds__(256)
void ln_kernel(const float* __restrict__ x, const float* __restrict__ g,
               const float* __restrict__ b, __half* __restrict__ y)
{
    int row = blockIdx.x;
    int t = threadIdx.x;
    const float4* xr = reinterpret_cast<const float4*>(x + (size_t)row * Dq);
    float4 v = xr[t];
    float s  = v.x + v.y + v.z + v.w;
    float s2 = v.x*v.x + v.y*v.y + v.z*v.z + v.w*v.w;
    __shared__ float rs[8], rs2[8];
    #pragma unroll
    for (int o = 16; o > 0; o >>= 1) {
        s  += __shfl_down_sync(0xffffffffu, s,  o);
        s2 += __shfl_down_sync(0xffffffffu, s2, o);
    }
    if ((t & 31) == 0) { rs[t >> 5] = s; rs2[t >> 5] = s2; }
    __syncthreads();
    float ssum = 0.f, ssum2 = 0.f;
    #pragma unroll
    for (int i = 0; i < 8; i++) { ssum += rs[i]; ssum2 += rs2[i]; }
    float mu   = ssum * (1.0f / Dq);
    float var  = ssum2 * (1.0f / Dq) - mu * mu;
    float rstd = rsqrtf(var + 1e-5f);
    float4 gg = reinterpret_cast<const float4*>(g)[t];
    float4 bb = reinterpret_cast<const float4*>(b)[t];
    __half2 h01 = __floats2half2_rn((v.x - mu) * rstd * gg.x + bb.x,
                                    (v.y - mu) * rstd * gg.y + bb.y);
    __half2 h23 = __floats2half2_rn((v.z - mu) * rstd * gg.z + bb.z,
                                    (v.w - mu) * rstd * gg.w + bb.w);
    __half2* yp = reinterpret_cast<__half2*>(y + (size_t)row * Dq);
    yp[t * 2]     = h01;
    yp[t * 2 + 1] = h23;
}

__global__ void den_init(float* den) { den[blockIdx.x * 256 + threadIdx.x] = 1e-6f; }

// in [R,C] -> out [C,R], batched in z
template<typename Ti, typename To>
__global__ __launch_bounds__(256)
void tr_kernel(const Ti* __restrict__ in, To* __restrict__ out,
               int R, int C, long long sIn, long long sOut)
{
    __shared__ float t[32][33];
    const Ti* ib = in  + (size_t)blockIdx.z * sIn;
    To*       ob = out + (size_t)blockIdx.z * sOut;
    int c = blockIdx.x * 32 + threadIdx.x;
    int r = blockIdx.y * 32 + threadIdx.y;
    #pragma unroll
    for (int dy = 0; dy < 32; dy += 8)
        t[threadIdx.y + dy][threadIdx.x] = ldf(&ib[(size_t)(r + dy) * C + c]);
    __syncthreads();
    int c2 = blockIdx.y * 32 + threadIdx.x;
    int r2 = blockIdx.x * 32 + threadIdx.y;
    #pragma unroll
    for (int dy = 0; dy < 32; dy += 8)
        ob[(size_t)(r2 + dy) * R + c2] = (To)t[threadIdx.x][threadIdx.y + dy];
}

// ---------------- fp16 mma.sync GEMM: 128x128 CTA, 8 warps (2Mx4N), warp 64x32 ----------------
__device__ __forceinline__ float gelu_exact(float v) {
    return 0.5f * v * (1.0f + erff(v * 0.70710678118654752f));
}
enum { EPI_BIAS = 0, EPI_FEAT = 1, EPI_GELU = 2, EPI_BIAS_RES = 3, EPI_DIV = 4, EPI_SCORE = 5 };
// CM: 0 none, 1 score-causal (skip upper tiles, mask, rowsum->den), 2 PV (K limited to r0+128)

#define MM_SMEM (3 * 32768 + 1024)

template<int EPI, int CM, typename OutT>
__global__ __launch_bounds__(256, 1)
void mm_kernel(const __half* __restrict__ A, const __half* __restrict__ Bm, OutT* __restrict__ C,
               int ldA, int ldB, int ldC, int Kdim,
               long long sA, long long sB, long long sC,
               const float* __restrict__ bias,
               const float* __restrict__ res, long long sRes,
               float* __restrict__ den, int denB)
{
    int bz = blockIdx.z;
    int r0 = blockIdx.y * 128, c0 = blockIdx.x * 128;
    if (CM == 1 && c0 > r0) return;
    const int keff = (CM == 2) ? (r0 + 128) : Kdim;
    const int nc = keff >> 6;                 // 64-half K chunks (128B per row)

    const __half* Ab = A  + (size_t)bz * sA;
    const __half* Bb = Bm + (size_t)bz * sB;
    OutT*         Cb = C  + (size_t)bz * sC;

    extern __shared__ char dsm[];
    uint32_t s0 = (smem_u32(dsm) + 1023u) & ~1023u;   // stage s: A at s*32768, B at +16384

    int tid = threadIdx.x;

    // ---- loader: each thread does 4 A + 4 B cp.async of 16B per chunk ----
    int lm = tid >> 1;                 // row 0..127
    int cbase = (tid & 1) * 4;         // 16B-chunk base within 8 chunks per 128B row
    const __half* gA = Ab + (size_t)(r0 + lm) * ldA + cbase * 8;
    const __half* gB = Bb + (size_t)(c0 + lm) * ldB + cbase * 8;
    uint32_t sw[4];
    #pragma unroll
    for (int i = 0; i < 4; i++)
        sw[i] = (uint32_t)lm * 128u + (uint32_t)(((cbase + i) ^ (lm & 7)) << 4);

    // prologue: chunks 0..2
    #pragma unroll
    for (int j = 0; j < 3; j++) {
        uint32_t aB = s0 + j * 32768, bB = aB + 16384;
        #pragma unroll
        for (int i = 0; i < 4; i++) {
            cp16(aB + sw[i], gA + j * 64 + i * 8);
            cp16(bB + sw[i], gB + j * 64 + i * 8);
        }
        CP_COMMIT();
    }

    // ---- fragment address bases ----
    int lane = tid & 31;
    int wm = (tid >> 5) & 1;           // 2 warps in M (64 rows each)
    int wn = tid >> 6;                 // 4 warps in N (32 cols each)
    int aRow = wm * 64 + (lane & 15);  // + mt*16
    int aHalf = lane >> 4;             // which 16B chunk within k16 (2 chunks)
    int bg = lane >> 3;
    int bRow = wn * 32 + ((bg >> 1) * 8) + (lane & 7);  // + nt(pair)*16
    int bHalf = bg & 1;
    uint32_t aOff = (uint32_t)aRow * 128u;
    uint32_t bOff = (uint32_t)bRow * 128u;
    int aR7 = aRow & 7, bR7 = bRow & 7;

    float c[4][4][4];
    #pragma unroll
    for (int mt = 0; mt < 4; mt++)
        #pragma unroll
        for (int nt = 0; nt < 4; nt++)
            #pragma unroll
            for (int k = 0; k < 4; k++) c[mt][nt][k] = 0.f;

    for (int i = 0; i < nc; i++) {
        int s = i - (i / 3) * 3;
        CP_WAIT2();
        __syncthreads();
        uint32_t aB = s0 + s * 32768, bB = aB + 16384;
        #pragma unroll
        for (int ks = 0; ks < 4; ks++) {      // 4 k16 steps per 64-half chunk
            uint32_t a[4][4];
            #pragma unroll
            for (int mt = 0; mt < 4; mt++) {
                uint32_t ad = aB + aOff + (uint32_t)(mt * 16 * 128)
                            + (uint32_t)(((ks * 2 + aHalf) ^ aR7) << 4);
                ldsm4(a[mt], ad);
            }
            uint32_t b[8];
            #pragma unroll
            for (int np = 0; np < 2; np++) {
                uint32_t bd = bB + bOff + (uint32_t)(np * 16 * 128)
                            + (uint32_t)(((ks * 2 + bHalf) ^ bR7) << 4);
                uint32_t r[4];
                ldsm4(r, bd);
                b[np*4+0]=r[0]; b[np*4+1]=r[1]; b[np*4+2]=r[2]; b[np*4+3]=r[3];
            }
            // b regs: {n0-7 khalf0, n0-7 khalf1, n8-15 khalf0, n8-15 khalf1} per np
            #pragma unroll
            for (int mt = 0; mt < 4; mt++) {
                mma_f16(c[mt][0], a[mt], b[0], b[1]);
                mma_f16(c[mt][1], a[mt], b[2], b[3]);
                mma_f16(c[mt][2], a[mt], b[4], b[5]);
                mma_f16(c[mt][3], a[mt], b[6], b[7]);
            }
        }
        __syncthreads();
        if (i + 3 < nc) {
            int j = i + 3;
            uint32_t aB2 = s0 + s * 32768, bB2 = aB2 + 16384;
            #pragma unroll
            for (int ii = 0; ii < 4; ii++) {
                cp16(aB2 + sw[ii], gA + j * 64 + ii * 8);
                cp16(bB2 + sw[ii], gB + j * 64 + ii * 8);
            }
        }
        CP_COMMIT();
    }

    // ---- epilogue ----
    int g4 = lane >> 2, q4 = lane & 3;
    #pragma unroll
    for (int mt = 0; mt < 4; mt++) {
        int row0 = r0 + wm * 64 + mt * 16 + g4;
        int row1 = row0 + 8;
        float d0 = 1.f, d1 = 1.f;
        if (EPI == EPI_DIV) {
            d0 = 1.0f / den[(size_t)bz * denB + row0];
            d1 = 1.0f / den[(size_t)bz * denB + row1];
        }
        float rs0 = 0.f, rs1 = 0.f;
        #pragma unroll
        for (int nt = 0; nt < 4; nt++) {
            int col = c0 + wn * 32 + nt * 8 + q4 * 2;
            float v0 = c[mt][nt][0], v1 = c[mt][nt][1];
            float v2 = c[mt][nt][2], v3 = c[mt][nt][3];
            if (EPI == EPI_BIAS || EPI == EPI_FEAT || EPI == EPI_GELU || EPI == EPI_BIAS_RES) {
                float2 bv = *reinterpret_cast<const float2*>(bias + col);
                v0 += bv.x; v1 += bv.y; v2 += bv.x; v3 += bv.y;
            }
            if (EPI == EPI_FEAT) {
                v0 = (v0 > 0.f) ? (v0 + 1.f) : expf(v0);
                v1 = (v1 > 0.f) ? (v1 + 1.f) : expf(v1);
                v2 = (v2 > 0.f) ? (v2 + 1.f) : expf(v2);
                v3 = (v3 > 0.f) ? (v3 + 1.f) : expf(v3);
            }
            if (EPI == EPI_GELU) {
                v0 = gelu_exact(v0); v1 = gelu_exact(v1);
                v2 = gelu_exact(v2); v3 = gelu_exact(v3);
            }
            if (EPI == EPI_BIAS_RES) {
                const float* rp0 = res + (size_t)bz * sRes + (size_t)row0 * ldC + col;
                const float* rp1 = res + (size_t)bz * sRes + (size_t)row1 * ldC + col;
                float2 r0v = *reinterpret_cast<const float2*>(rp0);
                float2 r1v = *reinterpret_cast<const float2*>(rp1);
                v0 += r0v.x; v1 += r0v.y; v2 += r1v.x; v3 += r1v.y;
            }
            if (EPI == EPI_DIV) {
                v0 *= d0; v1 *= d0; v2 *= d1; v3 *= d1;
            }
            if (EPI == EPI_SCORE) {
                if (col     > row0) v0 = 0.f;
                if (col + 1 > row0) v1 = 0.f;
                if (col     > row1) v2 = 0.f;
                if (col + 1 > row1) v3 = 0.f;
                rs0 += v0 + v1; rs1 += v2 + v3;
            }
            st2(Cb + (size_t)row0 * ldC + col, v0, v1);
            st2(Cb + (size_t)row1 * ldC + col, v2, v3);
        }
        if (EPI == EPI_SCORE) {
            atomicAdd(&den[(size_t)bz * denB + row0], rs0);
            atomicAdd(&den[(size_t)bz * denB + row1], rs1);
        }
    }
}

// ---------------- launch ----------------
extern "C" void kernel_launch(void* const* d_in, const int* in_sizes, int n_in,
                              void* d_out, int out_size)
{
    const float* x     = (const float*)d_in[0];
    const float* q_w   = (const float*)d_in[1];
    const float* q_b   = (const float*)d_in[2];
    const float* k_w   = (const float*)d_in[3];
    const float* k_b   = (const float*)d_in[4];
    const float* v_w   = (const float*)d_in[5];
    const float* v_b   = (const float*)d_in[6];
    const float* o_w   = (const float*)d_in[7];
    const float* o_b   = (const float*)d_in[8];
    const float* ln1_g = (const float*)d_in[9];
    const float* ln1_b = (const float*)d_in[10];
    const float* ln2_g = (const float*)d_in[11];
    const float* ln2_b = (const float*)d_in[12];
    const float* w1    = (const float*)d_in[13];
    const float* b1    = (const float*)d_in[14];
    const float* w2    = (const float*)d_in[15];
    const float* b2    = (const float*)d_in[16];
    float* out = (float*)d_out;

    __half *xn, *Qp, *Kp, *Vp, *Vt, *Pp, *attn, *xn2, *h;
    __half *qT, *kT, *vT, *oT, *w1T, *w2T;
    float *den, *x1;
    cudaGetSymbolAddress((void**)&xn,   g_xn);
    cudaGetSymbolAddress((void**)&Qp,   g_Q);
    cudaGetSymbolAddress((void**)&Kp,   g_K);
    cudaGetSymbolAddress((void**)&Vp,   g_V);
    cudaGetSymbolAddress((void**)&Vt,   g_Vt);
    cudaGetSymbolAddress((void**)&Pp,   g_P);
    cudaGetSymbolAddress((void**)&den,  g_den);
    cudaGetSymbolAddress((void**)&attn, g_attn);
    cudaGetSymbolAddress((void**)&x1,   g_x1);
    cudaGetSymbolAddress((void**)&xn2,  g_xn2);
    cudaGetSymbolAddress((void**)&h,    g_h);
    cudaGetSymbolAddress((void**)&qT,   g_qT);
    cudaGetSymbolAddress((void**)&kT,   g_kT);
    cudaGetSymbolAddress((void**)&vT,   g_vT);
    cudaGetSymbolAddress((void**)&oT,   g_oT);
    cudaGetSymbolAddress((void**)&w1T,  g_w1T);
    cudaGetSymbolAddress((void**)&w2T,  g_w2T);

    cudaFuncSetAttribute(mm_kernel<EPI_FEAT, 0, __half>,    cudaFuncAttributeMaxDynamicSharedMemorySize, MM_SMEM);
    cudaFuncSetAttribute(mm_kernel<EPI_BIAS, 0, __half>,    cudaFuncAttributeMaxDynamicSharedMemorySize, MM_SMEM);
    cudaFuncSetAttribute(mm_kernel<EPI_SCORE, 1, __half>,   cudaFuncAttributeMaxDynamicSharedMemorySize, MM_SMEM);
    cudaFuncSetAttribute(mm_kernel<EPI_DIV, 2, __half>,     cudaFuncAttributeMaxDynamicSharedMemorySize, MM_SMEM);
    cudaFuncSetAttribute(mm_kernel<EPI_BIAS_RES, 0, float>, cudaFuncAttributeMaxDynamicSharedMemorySize, MM_SMEM);
    cudaFuncSetAttribute(mm_kernel<EPI_GELU, 0, __half>,    cudaFuncAttributeMaxDynamicSharedMemorySize, MM_SMEM);

    dim3 tb(32, 8);

    // LN1 -> fp16
    ln_kernel<<<Mq, 256>>>(x, ln1_g, ln1_b, xn);

    // weight transposes -> [N, K] K-major fp16
    tr_kernel<float, __half><<<dim3(Eq/32, Dq/32, 1), tb>>>(q_w, qT, Dq, Eq, 0, 0);
    tr_kernel<float, __half><<<dim3(Eq/32, Dq/32, 1), tb>>>(k_w, kT, Dq, Eq, 0, 0);
    tr_kernel<float, __half><<<dim3(Eq/32, Dq/32, 1), tb>>>(v_w, vT, Dq, Eq, 0, 0);
    tr_kernel<float, __half><<<dim3(Dq/32, Eq/32, 1), tb>>>(o_w, oT, Eq, Dq, 0, 0);
    tr_kernel<float, __half><<<dim3(Fq/32, Dq/32, 1), tb>>>(w1, w1T, Dq, Fq, 0, 0);
    tr_kernel<float, __half><<<dim3(Dq/32, Fq/32, 1), tb>>>(w2, w2T, Fq, Dq, 0, 0);

    // Q/K/V projections
    mm_kernel<EPI_FEAT, 0, __half><<<dim3(Eq/128, Mq/128, 1), 256, MM_SMEM>>>(
        xn, qT, Qp, Dq, Dq, Eq, Dq, 0, 0, 0, q_b, nullptr, 0, nullptr, 0);
    mm_kernel<EPI_FEAT, 0, __half><<<dim3(Eq/128, Mq/128, 1), 256, MM_SMEM>>>(
        xn, kT, Kp, Dq, Dq, Eq, Dq, 0, 0, 0, k_b, nullptr, 0, nullptr, 0);
    mm_kernel<EPI_BIAS, 0, __half><<<dim3(Eq/128, Mq/128, 1), 256, MM_SMEM>>>(
        xn, vT, Vp, Dq, Dq, Eq, Dq, 0, 0, 0, v_b, nullptr, 0, nullptr, 0);

    // V^T per batch: [Nq, Eq] -> [Eq, Nq]
    tr_kernel<__half, __half><<<dim3(Eq/32, Nq/32, Bq), tb>>>(Vp, Vt, Nq, Eq,
        (long long)Nq * Eq, (long long)Nq * Eq);

    // scores: P = tril(Q K^T); den = rowsum + 1e-6
    den_init<<<Mq/256, 256>>>(den);
    mm_kernel<EPI_SCORE, 1, __half><<<dim3(Nq/128, Nq/128, Bq), 256, MM_SMEM>>>(
        Qp, Kp, Pp, Eq, Eq, Nq, Eq,
        (long long)Nq * Eq, (long long)Nq * Eq, (long long)Nq * Nq,
        nullptr, nullptr, 0, den, Nq);

    // attn = (P @ V) / den  (B operand = V^T, K limited per tile row)
    mm_kernel<EPI_DIV, 2, __half><<<dim3(Eq/128, Nq/128, Bq), 256, MM_SMEM>>>(
        Pp, Vt, attn, Nq, Nq, Eq, Nq,
        (long long)Nq * Nq, (long long)Nq * Eq, (long long)Nq * Eq,
        nullptr, nullptr, 0, den, Nq);

    // output projection + residual (fp32 out)
    mm_kernel<EPI_BIAS_RES, 0, float><<<dim3(Dq/128, Mq/128, 1), 256, MM_SMEM>>>(
        attn, oT, x1, Eq, Eq, Dq, Eq, 0, 0, 0, o_b, x, 0, nullptr, 0);

    // LN2 + FFN
    ln_kernel<<<Mq, 256>>>(x1, ln2_g, ln2_b, xn2);
    mm_kernel<EPI_GELU, 0, __half><<<dim3(Fq/128, Mq/128, 1), 256, MM_SMEM>>>(
        xn2, w1T, h, Dq, Dq, Fq, Dq, 0, 0, 0, b1, nullptr, 0, nullptr, 0);
    mm_kernel<EPI_BIAS_RES, 0, float><<<dim3(Dq/128, Mq/128, 1), 256, MM_SMEM>>>(
        h, w2T, out, Fq, Fq, Dq, Fq, 0, 0, 0, b2, x1, 0, nullptr, 0);
}